// round 11
// baseline (speedup 1.0000x reference)
#include <cuda_runtime.h>

// ---------------------------------------------------------------------------
// StockLSTM: batch-vectorized packed-f32x2 persistent LSTM.  Round 11:
//   - REVERT R9/R10 h-read widening (regressed: uniform LDS.128 didn't halve
//     wavefronts, added alu/regs).  Back to R8 per-k LDS.64 broadcasts.
//   - KEEP h1 double-buffer.
//   - RESTRUCTURE step: layer1 recurrent half (Whh1*h2(t-1)) computed BEFORE
//     layer0 epilogue/barrier -> independent fma stream overlaps the MUFU
//     chain; only Wih1*h1(t) remains after the barrier.
//   - 2 barriers/step (bar A covers h1 publish + h2/x WAR; bar C covers h2
//     publish + x-chunk staging folded in).
// ---------------------------------------------------------------------------

#define B_      4096
#define T_      256
#define I_      5
#define H_      64
#define O_      25
#define NBT     8
#define BP      4
#define GROUPS  4
#define THREADS 256
#define TCH     4

typedef unsigned long long ull;

__device__ float4 gW0h[H_ * H_];
__device__ float4 gW1x[H_ * H_];
__device__ float4 gW1h[H_ * H_];
__device__ float4 gW0x[I_ * H_];
__device__ float4 gBias0[H_];
__device__ float4 gBias1[H_];

__global__ void prep_kernel(const float* __restrict__ Wih0, const float* __restrict__ Whh0,
                            const float* __restrict__ bih0, const float* __restrict__ bhh0,
                            const float* __restrict__ Wih1, const float* __restrict__ Whh1,
                            const float* __restrict__ bih1, const float* __restrict__ bhh1)
{
    const int stride = gridDim.x * blockDim.x;
    const int tid0   = blockIdx.x * blockDim.x + threadIdx.x;

    for (int idx = tid0; idx < H_ * H_; idx += stride) {
        const int k = idx >> 6, j = idx & 63;
        gW0h[idx] = make_float4(Whh0[j*H_+k],        Whh0[(H_+j)*H_+k],
                                Whh0[(2*H_+j)*H_+k], Whh0[(3*H_+j)*H_+k]);
        gW1x[idx] = make_float4(Wih1[j*H_+k],        Wih1[(H_+j)*H_+k],
                                Wih1[(2*H_+j)*H_+k], Wih1[(3*H_+j)*H_+k]);
        gW1h[idx] = make_float4(Whh1[j*H_+k],        Whh1[(H_+j)*H_+k],
                                Whh1[(2*H_+j)*H_+k], Whh1[(3*H_+j)*H_+k]);
    }
    for (int idx = tid0; idx < I_ * H_; idx += stride) {
        const int k = idx >> 6, j = idx & 63;
        gW0x[idx] = make_float4(Wih0[j*I_+k],        Wih0[(H_+j)*I_+k],
                                Wih0[(2*H_+j)*I_+k], Wih0[(3*H_+j)*I_+k]);
    }
    for (int j = tid0; j < H_; j += stride) {
        gBias0[j] = make_float4(bih0[j]      + bhh0[j],
                                bih0[H_+j]   + bhh0[H_+j],
                                bih0[2*H_+j] + bhh0[2*H_+j],
                                bih0[3*H_+j] + bhh0[3*H_+j]);
        gBias1[j] = make_float4(bih1[j]      + bhh1[j],
                                bih1[H_+j]   + bhh1[H_+j],
                                bih1[2*H_+j] + bhh1[2*H_+j],
                                bih1[3*H_+j] + bhh1[3*H_+j]);
    }
}

__device__ __forceinline__ ull dup2(float v) {
    ull r; asm("mov.b64 %0, {%1, %1};" : "=l"(r) : "f"(v)); return r;
}
__device__ __forceinline__ void unpk(float& lo, float& hi, ull v) {
    asm("mov.b64 {%0, %1}, %2;" : "=f"(lo), "=f"(hi) : "l"(v));
}
__device__ __forceinline__ void fma2(ull& d, ull a, ull b) {
    asm("fma.rn.f32x2 %0, %1, %2, %3;" : "=l"(d) : "l"(a), "l"(b), "l"(d));
}
__device__ __forceinline__ float sigm(float v)   { return __fdividef(1.f, 1.f + __expf(-v)); }
__device__ __forceinline__ float tanh_f(float v) { return __fdividef(2.f, 1.f + __expf(-2.f * v)) - 1.f; }
__device__ __forceinline__ void barg(int g) {
    asm volatile("bar.sync %0, 64;" :: "r"(1 + g) : "memory");
}

// SMEM: 201728 B weights + (4096+2048+640)*4 B dyn = 228864 B  (1 blk/SM)
#define SM_BYTES 228864

__global__ __launch_bounds__(THREADS)
void lstm_kernel(const float* __restrict__ x,
                 const float* __restrict__ Wfc, const float* __restrict__ bfc,
                 float* __restrict__ out)
{
    extern __shared__ float4 smem[];
    float4* sW0h = smem;                    // 4096 float4
    float4* sW1x = smem + 4096;             // 4096
    float4* sW1h = smem + 8192;             // 4096
    float4* sW0x = smem + 12288;            // 320
    float*  sf   = reinterpret_cast<float*>(smem + 12608);
    float*  h1T  = sf;                      // [2 buf][4 grp][BP][64][2] = 4096 f
    float*  h2T  = sf + 4096;               // [4 grp][BP][64][2]        = 2048 f
    float*  sxT  = sf + 6144;               // [4 grp][BP][TCH*5][2]     = 640 f

    const int tid = threadIdx.x;

    for (int i = tid; i < H_ * H_; i += THREADS) {
        sW0h[i] = gW0h[i]; sW1x[i] = gW1x[i]; sW1h[i] = gW1h[i];
    }
    for (int i = tid; i < I_ * H_; i += THREADS) sW0x[i] = gW0x[i];
    for (int i = tid; i < 6144; i += THREADS) h1T[i] = 0.f;   // h1 bufs + h2

    const int g  = tid >> 6;
    const int j  = tid & 63;
    const int b0 = blockIdx.x * (GROUPS * NBT) + g * NBT;

    float* h1g = h1T + g * (BP * H_ * 2);               // + buf*2048
    float* h2  = h2T + g * (BP * H_ * 2);
    float* sx  = sxT + g * (BP * TCH * I_ * 2);

    // stage x chunk for steps [0,4) before the global sync
    for (int i = j; i < NBT * TCH * I_; i += 64) {
        const int bl = i & 7;
        const int r  = i >> 3;
        const int bp = bl >> 1, e = bl & 1;
        sx[bp * (TCH * I_ * 2) + r * 2 + e]
            = x[(size_t)(b0 + bl) * (T_ * I_) + 0 * I_ + r];
    }
    __syncthreads();

    const float4 bv0 = gBias0[j];
    const float4 bv1 = gBias1[j];
    const ull bi0 = dup2(bv0.x), bf0 = dup2(bv0.y), bg0 = dup2(bv0.z), bo0 = dup2(bv0.w);
    const ull bi1 = dup2(bv1.x), bf1 = dup2(bv1.y), bg1 = dup2(bv1.z), bo1 = dup2(bv1.w);

    float c1[NBT], c2[NBT];
#pragma unroll
    for (int b = 0; b < NBT; ++b) { c1[b] = 0.f; c2[b] = 0.f; }

    ull a0i[BP], a0f[BP], a0g[BP], a0o[BP];     // layer0 accums
    ull a1i[BP], a1f[BP], a1g[BP], a1o[BP];     // layer1 accums (live across bar A)

#pragma unroll 1
    for (int t = 0; t < T_; ++t) {
        const float* h1r = h1g + (t & 1) * 2048;        // h1(t-1)
        float*       h1w = h1g + ((t + 1) & 1) * 2048;  // h1(t)

        // ---- layer1 recurrent half: a1 = bias1 + Whh1 * h2(t-1) ----
#pragma unroll
        for (int bp = 0; bp < BP; ++bp) { a1i[bp]=bi1; a1f[bp]=bf1; a1g[bp]=bg1; a1o[bp]=bo1; }
#pragma unroll 8
        for (int k = 0; k < H_; ++k) {
            const float4 w = sW1h[k * H_ + j];
            const ull wi = dup2(w.x), wf = dup2(w.y), wg = dup2(w.z), wo = dup2(w.w);
#pragma unroll
            for (int bp = 0; bp < BP; ++bp) {
                const ull hv = *reinterpret_cast<const ull*>(h2 + bp * 128 + k * 2);
                fma2(a1i[bp], wi, hv); fma2(a1f[bp], wf, hv);
                fma2(a1g[bp], wg, hv); fma2(a1o[bp], wo, hv);
            }
        }

        // ---- layer0 full matvec ----
#pragma unroll
        for (int bp = 0; bp < BP; ++bp) { a0i[bp]=bi0; a0f[bp]=bf0; a0g[bp]=bg0; a0o[bp]=bo0; }
#pragma unroll 8
        for (int k = 0; k < H_; ++k) {
            const float4 w = sW0h[k * H_ + j];
            const ull wi = dup2(w.x), wf = dup2(w.y), wg = dup2(w.z), wo = dup2(w.w);
#pragma unroll
            for (int bp = 0; bp < BP; ++bp) {
                const ull hv = *reinterpret_cast<const ull*>(h1r + bp * 128 + k * 2);
                fma2(a0i[bp], wi, hv); fma2(a0f[bp], wf, hv);
                fma2(a0g[bp], wg, hv); fma2(a0o[bp], wo, hv);
            }
        }
#pragma unroll
        for (int k = 0; k < I_; ++k) {
            const float4 w = sW0x[k * H_ + j];
            const ull wi = dup2(w.x), wf = dup2(w.y), wg = dup2(w.z), wo = dup2(w.w);
            const int xoff = ((t & (TCH - 1)) * I_ + k) * 2;
#pragma unroll
            for (int bp = 0; bp < BP; ++bp) {
                const ull xv = *reinterpret_cast<const ull*>(sx + bp * (TCH * I_ * 2) + xoff);
                fma2(a0i[bp], wi, xv); fma2(a0f[bp], wf, xv);
                fma2(a0g[bp], wg, xv); fma2(a0o[bp], wo, xv);
            }
        }

        // ---- layer0 epilogue -> publish h1(t) ----
#pragma unroll
        for (int bp = 0; bp < BP; ++bp) {
            float i0,i1,f0,f1,g0,g1,o0,o1;
            unpk(i0,i1,a0i[bp]); unpk(f0,f1,a0f[bp]); unpk(g0,g1,a0g[bp]); unpk(o0,o1,a0o[bp]);
            const float cA = sigm(f0)*c1[2*bp]   + sigm(i0)*tanh_f(g0);
            const float cB = sigm(f1)*c1[2*bp+1] + sigm(i1)*tanh_f(g1);
            c1[2*bp]   = cA;
            c1[2*bp+1] = cB;
            *reinterpret_cast<float2*>(h1w + bp * 128 + j * 2)
                = make_float2(sigm(o0)*tanh_f(cA), sigm(o1)*tanh_f(cB));
        }
        barg(g);        // bar A: h1(t) visible; readers of h2(t-1)/x-chunk done

        // ---- layer1 input half: a1 += Wih1 * h1(t) ----
#pragma unroll 8
        for (int k = 0; k < H_; ++k) {
            const float4 w = sW1x[k * H_ + j];
            const ull wi = dup2(w.x), wf = dup2(w.y), wg = dup2(w.z), wo = dup2(w.w);
#pragma unroll
            for (int bp = 0; bp < BP; ++bp) {
                const ull xv = *reinterpret_cast<const ull*>(h1w + bp * 128 + k * 2);
                fma2(a1i[bp], wi, xv); fma2(a1f[bp], wf, xv);
                fma2(a1g[bp], wg, xv); fma2(a1o[bp], wo, xv);
            }
        }

        // ---- layer1 epilogue -> publish h2(t) ----
#pragma unroll
        for (int bp = 0; bp < BP; ++bp) {
            float i0,i1,f0,f1,g0,g1,o0,o1;
            unpk(i0,i1,a1i[bp]); unpk(f0,f1,a1f[bp]); unpk(g0,g1,a1g[bp]); unpk(o0,o1,a1o[bp]);
            const float cA = sigm(f0)*c2[2*bp]   + sigm(i0)*tanh_f(g0);
            const float cB = sigm(f1)*c2[2*bp+1] + sigm(i1)*tanh_f(g1);
            c2[2*bp]   = cA;
            c2[2*bp+1] = cB;
            *reinterpret_cast<float2*>(h2 + bp * 128 + j * 2)
                = make_float2(sigm(o0)*tanh_f(cA), sigm(o1)*tanh_f(cB));
        }

        // ---- stage x chunk for steps [t+1, t+5) (current chunk fully read) ----
        if (((t + 1) & (TCH - 1)) == 0 && (t + 1) < T_) {
            const int tb = t + 1;
            for (int i = j; i < NBT * TCH * I_; i += 64) {
                const int bl = i & 7;
                const int r  = i >> 3;
                const int bp = bl >> 1, e = bl & 1;
                sx[bp * (TCH * I_ * 2) + r * 2 + e]
                    = x[(size_t)(b0 + bl) * (T_ * I_) + tb * I_ + r];
            }
        }
        barg(g);        // bar C: h2(t) + new x chunk visible
    }

    // ---- FC on h2(T-1) ----
    for (int i = j; i < NBT * O_; i += 64) {
        const int bl = i / O_;
        const int o  = i - bl * O_;
        const int bp = bl >> 1, e = bl & 1;
        const float* wrow = Wfc + o * H_;
        float acc = bfc[o];
#pragma unroll 8
        for (int k = 0; k < H_; ++k)
            acc += h2[bp * 128 + k * 2 + e] * wrow[k];
        out[(size_t)(b0 + bl) * O_ + o] = acc;
    }
}

// ---------------------------------------------------------------------------
extern "C" void kernel_launch(void* const* d_in, const int* in_sizes, int n_in,
                              void* d_out, int out_size)
{
    (void)in_sizes; (void)n_in; (void)out_size;
    const float* x    = (const float*)d_in[0];
    const float* Wih0 = (const float*)d_in[1];
    const float* Whh0 = (const float*)d_in[2];
    const float* bih0 = (const float*)d_in[3];
    const float* bhh0 = (const float*)d_in[4];
    const float* Wih1 = (const float*)d_in[5];
    const float* Whh1 = (const float*)d_in[6];
    const float* bih1 = (const float*)d_in[7];
    const float* bhh1 = (const float*)d_in[8];
    const float* Wfc  = (const float*)d_in[9];
    const float* bfc  = (const float*)d_in[10];
    float* out = (float*)d_out;

    cudaFuncSetAttribute(lstm_kernel, cudaFuncAttributeMaxDynamicSharedMemorySize,
                         SM_BYTES);

    prep_kernel<<<32, 256>>>(Wih0, Whh0, bih0, bhh0, Wih1, Whh1, bih1, bhh1);
    lstm_kernel<<<B_ / (GROUPS * NBT), THREADS, SM_BYTES>>>(x, Wfc, bfc, out);
}

// round 12
// speedup vs baseline: 1.1322x; 1.1322x over previous
#include <cuda_runtime.h>

// ---------------------------------------------------------------------------
// StockLSTM: batch-vectorized packed-f32x2 persistent LSTM.
// Round 12 = exact R8 structure (best: 2268us) + ONE change:
//   activations via HW tanh.approx.f32 (1 MUFU) instead of EX2+RCP (2 MUFU);
//   sigmoid(x) = 0.5*tanh(0.5x)+0.5.  Halves the epilogue MUFU phase
//   (~2560 -> ~1300 cyc/step/SMSP), which is the dominant stall gap.
// Structure: block = 256 thr = 4 groups of 64; group = 64 cells x 8 batch
// (4 packed f32x2 pairs).  Weights float4[k][j]=(wi,wf,wg,wo) in SMEM;
// per k: 1 LDS.128 (conflict-free) + 4 dup + 4 broadcast LDS.64 + 16 fma2.
// ---------------------------------------------------------------------------

#define B_      4096
#define T_      256
#define I_      5
#define H_      64
#define O_      25
#define NBT     8
#define BP      4
#define GROUPS  4
#define THREADS 256
#define TCH     4

typedef unsigned long long ull;

__device__ float4 gW0h[H_ * H_];
__device__ float4 gW1x[H_ * H_];
__device__ float4 gW1h[H_ * H_];
__device__ float4 gW0x[I_ * H_];
__device__ float4 gBias0[H_];
__device__ float4 gBias1[H_];

__global__ void prep_kernel(const float* __restrict__ Wih0, const float* __restrict__ Whh0,
                            const float* __restrict__ bih0, const float* __restrict__ bhh0,
                            const float* __restrict__ Wih1, const float* __restrict__ Whh1,
                            const float* __restrict__ bih1, const float* __restrict__ bhh1)
{
    const int stride = gridDim.x * blockDim.x;
    const int tid0   = blockIdx.x * blockDim.x + threadIdx.x;

    for (int idx = tid0; idx < H_ * H_; idx += stride) {
        const int k = idx >> 6, j = idx & 63;
        gW0h[idx] = make_float4(Whh0[j*H_+k],        Whh0[(H_+j)*H_+k],
                                Whh0[(2*H_+j)*H_+k], Whh0[(3*H_+j)*H_+k]);
        gW1x[idx] = make_float4(Wih1[j*H_+k],        Wih1[(H_+j)*H_+k],
                                Wih1[(2*H_+j)*H_+k], Wih1[(3*H_+j)*H_+k]);
        gW1h[idx] = make_float4(Whh1[j*H_+k],        Whh1[(H_+j)*H_+k],
                                Whh1[(2*H_+j)*H_+k], Whh1[(3*H_+j)*H_+k]);
    }
    for (int idx = tid0; idx < I_ * H_; idx += stride) {
        const int k = idx >> 6, j = idx & 63;
        gW0x[idx] = make_float4(Wih0[j*I_+k],        Wih0[(H_+j)*I_+k],
                                Wih0[(2*H_+j)*I_+k], Wih0[(3*H_+j)*I_+k]);
    }
    for (int j = tid0; j < H_; j += stride) {
        gBias0[j] = make_float4(bih0[j]      + bhh0[j],
                                bih0[H_+j]   + bhh0[H_+j],
                                bih0[2*H_+j] + bhh0[2*H_+j],
                                bih0[3*H_+j] + bhh0[3*H_+j]);
        gBias1[j] = make_float4(bih1[j]      + bhh1[j],
                                bih1[H_+j]   + bhh1[H_+j],
                                bih1[2*H_+j] + bhh1[2*H_+j],
                                bih1[3*H_+j] + bhh1[3*H_+j]);
    }
}

__device__ __forceinline__ ull dup2(float v) {
    ull r; asm("mov.b64 %0, {%1, %1};" : "=l"(r) : "f"(v)); return r;
}
__device__ __forceinline__ void unpk(float& lo, float& hi, ull v) {
    asm("mov.b64 {%0, %1}, %2;" : "=f"(lo), "=f"(hi) : "l"(v));
}
__device__ __forceinline__ void fma2(ull& d, ull a, ull b) {
    asm("fma.rn.f32x2 %0, %1, %2, %3;" : "=l"(d) : "l"(a), "l"(b), "l"(d));
}
// HW tanh (single MUFU op).  sigmoid via tanh identity: 1 MUFU + 1 FMA.
__device__ __forceinline__ float tanh_f(float v) {
    float r; asm("tanh.approx.f32 %0, %1;" : "=f"(r) : "f"(v)); return r;
}
__device__ __forceinline__ float sigm(float v) {
    float r; asm("tanh.approx.f32 %0, %1;" : "=f"(r) : "f"(0.5f * v));
    return fmaf(r, 0.5f, 0.5f);
}
__device__ __forceinline__ void barg(int g) {
    asm volatile("bar.sync %0, 64;" :: "r"(1 + g) : "memory");
}

// SMEM: 201728 B weights + (2048+2048+640)*4 B dyn = 220672 B  (1 blk/SM)
#define SM_BYTES 220672

__global__ __launch_bounds__(THREADS)
void lstm_kernel(const float* __restrict__ x,
                 const float* __restrict__ Wfc, const float* __restrict__ bfc,
                 float* __restrict__ out)
{
    extern __shared__ float4 smem[];
    float4* sW0h = smem;                    // 4096 float4
    float4* sW1x = smem + 4096;             // 4096
    float4* sW1h = smem + 8192;             // 4096
    float4* sW0x = smem + 12288;            // 320
    float*  sf   = reinterpret_cast<float*>(smem + 12608);
    float*  h1T  = sf;                      // [4 grp][BP][64 k][2]  = 2048 f
    float*  h2T  = sf + 2048;               // 2048 f
    float*  sxT  = sf + 4096;               // [4 grp][BP][TCH*5][2] = 640 f

    const int tid = threadIdx.x;

    for (int i = tid; i < H_ * H_; i += THREADS) {
        sW0h[i] = gW0h[i]; sW1x[i] = gW1x[i]; sW1h[i] = gW1h[i];
    }
    for (int i = tid; i < I_ * H_; i += THREADS)
        sW0x[i] = gW0x[i];
    for (int i = tid; i < 2048; i += THREADS) { h1T[i] = 0.f; h2T[i] = 0.f; }
    __syncthreads();

    const int g  = tid >> 6;                // group (warp-uniform)
    const int j  = tid & 63;                // cell / lane-in-group
    const int b0 = blockIdx.x * (GROUPS * NBT) + g * NBT;

    float* h1 = h1T + g * (BP * H_ * 2);    // [bp*128 + k*2 + e]
    float* h2 = h2T + g * (BP * H_ * 2);
    float* sx = sxT + g * (BP * TCH * I_ * 2);

    const float4 bv0 = gBias0[j];
    const float4 bv1 = gBias1[j];
    const ull bi0 = dup2(bv0.x), bf0 = dup2(bv0.y), bg0 = dup2(bv0.z), bo0 = dup2(bv0.w);
    const ull bi1 = dup2(bv1.x), bf1 = dup2(bv1.y), bg1 = dup2(bv1.z), bo1 = dup2(bv1.w);

    float c1[NBT], c2[NBT];
#pragma unroll
    for (int b = 0; b < NBT; ++b) { c1[b] = 0.f; c2[b] = 0.f; }

    ull ai[BP], af[BP], ag[BP], ao[BP];

#pragma unroll 1
    for (int t = 0; t < T_; ++t) {
        // ---- stage x chunk (group-local) ----
        if ((t & (TCH - 1)) == 0) {
            for (int i = j; i < NBT * TCH * I_; i += 64) {
                const int bl = i & 7;
                const int r  = i >> 3;          // 0..19 = tt*5+kk
                const int bp = bl >> 1, e = bl & 1;
                sx[bp * (TCH * I_ * 2) + r * 2 + e]
                    = x[(size_t)(b0 + bl) * (T_ * I_) + t * I_ + r];
            }
            barg(g);
        }

        // ================= layer 0 =================
#pragma unroll
        for (int bp = 0; bp < BP; ++bp) { ai[bp]=bi0; af[bp]=bf0; ag[bp]=bg0; ao[bp]=bo0; }
#pragma unroll 8
        for (int k = 0; k < H_; ++k) {
            const float4 w = sW0h[k * H_ + j];
            const ull wi = dup2(w.x), wf = dup2(w.y), wg = dup2(w.z), wo = dup2(w.w);
#pragma unroll
            for (int bp = 0; bp < BP; ++bp) {
                const ull hv = *reinterpret_cast<const ull*>(h1 + bp * 128 + k * 2);
                fma2(ai[bp], wi, hv); fma2(af[bp], wf, hv);
                fma2(ag[bp], wg, hv); fma2(ao[bp], wo, hv);
            }
        }
#pragma unroll
        for (int k = 0; k < I_; ++k) {
            const float4 w = sW0x[k * H_ + j];
            const ull wi = dup2(w.x), wf = dup2(w.y), wg = dup2(w.z), wo = dup2(w.w);
            const int xoff = ((t & (TCH - 1)) * I_ + k) * 2;
#pragma unroll
            for (int bp = 0; bp < BP; ++bp) {
                const ull xv = *reinterpret_cast<const ull*>(sx + bp * (TCH * I_ * 2) + xoff);
                fma2(ai[bp], wi, xv); fma2(af[bp], wf, xv);
                fma2(ag[bp], wg, xv); fma2(ao[bp], wo, xv);
            }
        }
        float h1v[NBT];
#pragma unroll
        for (int bp = 0; bp < BP; ++bp) {
            float i0,i1,f0,f1,g0,g1,o0,o1;
            unpk(i0,i1,ai[bp]); unpk(f0,f1,af[bp]); unpk(g0,g1,ag[bp]); unpk(o0,o1,ao[bp]);
            const float cA = sigm(f0)*c1[2*bp]   + sigm(i0)*tanh_f(g0);
            const float cB = sigm(f1)*c1[2*bp+1] + sigm(i1)*tanh_f(g1);
            c1[2*bp]   = cA; h1v[2*bp]   = sigm(o0)*tanh_f(cA);
            c1[2*bp+1] = cB; h1v[2*bp+1] = sigm(o1)*tanh_f(cB);
        }
        barg(g);                               // all reads of h1(t-1) done
#pragma unroll
        for (int bp = 0; bp < BP; ++bp)
            *reinterpret_cast<float2*>(h1 + bp * 128 + j * 2) = make_float2(h1v[2*bp], h1v[2*bp+1]);
        barg(g);                               // h1(t) visible

        // ================= layer 1 =================
#pragma unroll
        for (int bp = 0; bp < BP; ++bp) { ai[bp]=bi1; af[bp]=bf1; ag[bp]=bg1; ao[bp]=bo1; }
#pragma unroll 4
        for (int k = 0; k < H_; ++k) {
            const float4 wx = sW1x[k * H_ + j];
            const float4 wh = sW1h[k * H_ + j];
            const ull xi = dup2(wx.x), xf = dup2(wx.y), xg = dup2(wx.z), xo = dup2(wx.w);
            const ull hi = dup2(wh.x), hf = dup2(wh.y), hg = dup2(wh.z), ho = dup2(wh.w);
#pragma unroll
            for (int bp = 0; bp < BP; ++bp) {
                const ull xv = *reinterpret_cast<const ull*>(h1 + bp * 128 + k * 2);
                const ull hv = *reinterpret_cast<const ull*>(h2 + bp * 128 + k * 2);
                fma2(ai[bp], xi, xv); fma2(af[bp], xf, xv);
                fma2(ag[bp], xg, xv); fma2(ao[bp], xo, xv);
                fma2(ai[bp], hi, hv); fma2(af[bp], hf, hv);
                fma2(ag[bp], hg, hv); fma2(ao[bp], ho, hv);
            }
        }
        float h2v[NBT];
#pragma unroll
        for (int bp = 0; bp < BP; ++bp) {
            float i0,i1,f0,f1,g0,g1,o0,o1;
            unpk(i0,i1,ai[bp]); unpk(f0,f1,af[bp]); unpk(g0,g1,ag[bp]); unpk(o0,o1,ao[bp]);
            const float cA = sigm(f0)*c2[2*bp]   + sigm(i0)*tanh_f(g0);
            const float cB = sigm(f1)*c2[2*bp+1] + sigm(i1)*tanh_f(g1);
            c2[2*bp]   = cA; h2v[2*bp]   = sigm(o0)*tanh_f(cA);
            c2[2*bp+1] = cB; h2v[2*bp+1] = sigm(o1)*tanh_f(cB);
        }
        barg(g);                               // all reads of h2(t-1) done
#pragma unroll
        for (int bp = 0; bp < BP; ++bp)
            *reinterpret_cast<float2*>(h2 + bp * 128 + j * 2) = make_float2(h2v[2*bp], h2v[2*bp+1]);
        barg(g);                               // h2(t) visible
    }

    // ---- FC on h2(T-1): out[b][o] = sum_k h2[k][b] * Wfc[o][k] + bfc[o] ----
    for (int i = j; i < NBT * O_; i += 64) {
        const int bl = i / O_;
        const int o  = i - bl * O_;
        const int bp = bl >> 1, e = bl & 1;
        const float* wrow = Wfc + o * H_;
        float acc = bfc[o];
#pragma unroll 8
        for (int k = 0; k < H_; ++k)
            acc += h2[bp * 128 + k * 2 + e] * wrow[k];
        out[(size_t)(b0 + bl) * O_ + o] = acc;
    }
}

// ---------------------------------------------------------------------------
extern "C" void kernel_launch(void* const* d_in, const int* in_sizes, int n_in,
                              void* d_out, int out_size)
{
    (void)in_sizes; (void)n_in; (void)out_size;
    const float* x    = (const float*)d_in[0];
    const float* Wih0 = (const float*)d_in[1];
    const float* Whh0 = (const float*)d_in[2];
    const float* bih0 = (const float*)d_in[3];
    const float* bhh0 = (const float*)d_in[4];
    const float* Wih1 = (const float*)d_in[5];
    const float* Whh1 = (const float*)d_in[6];
    const float* bih1 = (const float*)d_in[7];
    const float* bhh1 = (const float*)d_in[8];
    const float* Wfc  = (const float*)d_in[9];
    const float* bfc  = (const float*)d_in[10];
    float* out = (float*)d_out;

    cudaFuncSetAttribute(lstm_kernel, cudaFuncAttributeMaxDynamicSharedMemorySize,
                         SM_BYTES);

    prep_kernel<<<32, 256>>>(Wih0, Whh0, bih0, bhh0, Wih1, Whh1, bih1, bhh1);
    lstm_kernel<<<B_ / (GROUPS * NBT), THREADS, SM_BYTES>>>(x, Wfc, bfc, out);
}